// round 9
// baseline (speedup 1.0000x reference)
#include <cuda_runtime.h>
#include <cuda_bf16.h>

#define BB 64
#define TT 1024
#define DD 64
#define HH 4
#define SPLIT 8
#define RPC 128
#define STRIDE 68
#define NEGF (-4294967296.0f)

// ---------------- kernel A smem layout (floats) ----------------
#define OFF_KS   0                // 128*68 = 8704
#define OFF_P4   8704             // 512
#define OFF_ACC  9216             // 1024 (also rank0 u-scratch: part/q0/Qh)
#define OFF_U    10240            // 256
#define OFF_WRED 10496            // 32
#define OFF_MH   10528            // 4
#define ASM_FLOATS 10532
#define ASM_BYTES (ASM_FLOATS * 4)

// ---------------- kernel B smem layout (floats) ----------------
#define BF_WV    0                // 4096
#define BF_FW1   4096             // 16384
#define BF_FW2   20480            // 16384
#define BF_PACC  36864            // 2048  ([s][h][d] planar)
#define BF_FB1   38912            // 256
#define BF_FB2   39168            // 64
#define BF_Q0    39232            // 64
#define BF_MS    39296            // 32
#define BF_LS    39328            // 32
#define BF_FS    39360            // 32
#define BF_SC    39392            // 4
#define BF_QM    39396            // 4
#define BF_SSM   39400            // 256
#define BF_PART  39656            // 256
#define BF_RES   39912            // 64
#define BF_HID   39976            // 256
#define BSM_FLOATS 40232
#define BSM_BYTES (BSM_FLOATS * 4)

#define CP_ASYNC16(dst_u32, src) \
    asm volatile("cp.async.cg.shared.global [%0], [%1], 16;" :: "r"(dst_u32), "l"(src) : "memory")
#define CP_COMMIT() asm volatile("cp.async.commit_group;" ::: "memory")
#define CP_WAIT_GROUP(n) asm volatile("cp.async.wait_group %0;" :: "n"(n) : "memory")

// cross-kernel / cross-CTA scratch
__device__ float g_u[BB * 256];                      // [b][d*4+h]
__device__ float g_pacc[BB * SPLIT * HH * DD];       // [b][s][h][d] planar
__device__ float g_pm[BB * SPLIT * HH];
__device__ float g_pl[BB * SPLIT * HH];

// ============ A: cluster of 8 CTAs per batch. Rank 0 computes u while all
// key-tile DMAs fly; cluster barrier publishes it; then attention partials. ==
__global__ __launch_bounds__(256) __cluster_dims__(SPLIT, 1, 1)
void attn_partial_kernel(
    const float* __restrict__ queries, const float* __restrict__ keys,
    const int* __restrict__ key_mask,
    const float* __restrict__ W_Q, const float* __restrict__ W_K)
{
    extern __shared__ float sm[];
    const unsigned sbase = (unsigned)__cvta_generic_to_shared(sm);

    float*  ks   = sm + OFF_KS;
    float4* p4   = (float4*)(sm + OFF_P4);
    float4* accm = (float4*)(sm + OFF_ACC);
    float*  u    = sm + OFF_U;
    float*  wred = sm + OFF_WRED;
    float*  mh   = sm + OFF_MH;

    const int split = blockIdx.x;     // == cluster rank
    const int b     = blockIdx.y;
    const int t     = threadIdx.x;
    const int k0    = split * RPC;
    const int lane  = t & 31;
    const int wid   = t >> 5;

    // ---- key tile DMA: 128 rows x 16 f4, 8 per thread (all CTAs) ----
    {
        const float4* kg = (const float4*)(keys + ((size_t)b * TT + k0) * DD);
        #pragma unroll
        for (int i = 0; i < 8; i++) {
            int idx = t + i * 256;
            int row = idx >> 4, c = idx & 15;
            CP_ASYNC16(sbase + (row * STRIDE + c * 4) * 4, kg + idx);
        }
        CP_COMMIT();
    }
    int kmv = 1;
    if (t < RPC) kmv = key_mask[b * TT + k0 + t];

    // ---- rank 0: compute u = 0.25 * W_K-fold of (q0 @ W_Q) ----
    if (split == 0) {
        float* part = sm + OFF_ACC;          // 256 (reused; dead until scores)
        float* q0   = sm + OFF_ACC + 256;    // 64
        float* Qh   = sm + OFF_ACC + 320;    // 64

        if (t < 16) ((float4*)q0)[t] = ((const float4*)(queries + (size_t)b * TT * DD))[t];
        __syncthreads();
        {
            int j = t & 63, q = t >> 6;
            float a = 0.f;
            #pragma unroll
            for (int i = q * 16; i < q * 16 + 16; i++) a += q0[i] * W_Q[i * 64 + j];
            part[t] = a;
        }
        __syncthreads();
        if (t < 64) Qh[t] = part[t] + part[64 + t] + part[128 + t] + part[192 + t];
        __syncthreads();
        {
            int d = t & 63, h = t >> 6;
            const float4* wr  = (const float4*)(W_K + d * 64 + h * 16);
            const float4* qh4 = (const float4*)(Qh + h * 16);
            float s = 0.f;
            #pragma unroll
            for (int c = 0; c < 4; c++) {
                float4 w = wr[c]; float4 q = qh4[c];
                s += w.x * q.x + w.y * q.y + w.z * q.z + w.w * q.w;
            }
            s *= 0.25f;
            u[d * 4 + h] = s;                      // local copy for rank 0
            g_u[b * 256 + d * 4 + h] = s;          // publish for ranks 1..7
        }
        __threadfence();   // release g_u before cluster arrive
    }

    // ---- cluster barrier: u published ----
    asm volatile("barrier.cluster.arrive.aligned;" ::: "memory");
    asm volatile("barrier.cluster.wait.aligned;"   ::: "memory");

    if (split != 0 && t < 64) ((float4*)u)[t] = ((const float4*)g_u)[b * 64 + t];
    CP_WAIT_GROUP(0);
    __syncthreads();

    // ---- scores for key row t (threads 0..127), 4 heads ----
    if (t < RPC) {
        const float4* krow = (const float4*)&ks[t * STRIDE];
        const float4* u4 = (const float4*)u;
        float a0 = 0.f, a1 = 0.f, a2 = 0.f, a3 = 0.f;
        #pragma unroll
        for (int c = 0; c < 16; c++) {
            float4 kv = krow[c];
            float4 ux = u4[4 * c + 0], uy = u4[4 * c + 1];
            float4 uz = u4[4 * c + 2], uw = u4[4 * c + 3];
            a0 += kv.x * ux.x + kv.y * uy.x + kv.z * uz.x + kv.w * uw.x;
            a1 += kv.x * ux.y + kv.y * uy.y + kv.z * uz.y + kv.w * uw.y;
            a2 += kv.x * ux.z + kv.y * uy.z + kv.z * uz.z + kv.w * uw.z;
            a3 += kv.x * ux.w + kv.y * uy.w + kv.z * uz.w + kv.w * uw.w;
        }
        bool masked = (kmv != 1) || ((k0 + t) == 0);
        float s0 = masked ? NEGF : a0;
        float s1 = masked ? NEGF : a1;
        float s2 = masked ? NEGF : a2;
        float s3 = masked ? NEGF : a3;

        float m0 = s0, m1 = s1, m2 = s2, m3 = s3;
        #pragma unroll
        for (int o = 16; o; o >>= 1) {
            m0 = fmaxf(m0, __shfl_xor_sync(0xffffffffu, m0, o));
            m1 = fmaxf(m1, __shfl_xor_sync(0xffffffffu, m1, o));
            m2 = fmaxf(m2, __shfl_xor_sync(0xffffffffu, m2, o));
            m3 = fmaxf(m3, __shfl_xor_sync(0xffffffffu, m3, o));
        }
        if (lane == 0) {
            wred[wid * 4 + 0] = m0; wred[wid * 4 + 1] = m1;
            wred[wid * 4 + 2] = m2; wred[wid * 4 + 3] = m3;
        }
        p4[t] = make_float4(s0, s1, s2, s3);
    }
    __syncthreads();
    if (t < 4) {
        float m = wred[t];
        #pragma unroll
        for (int w = 1; w < 4; w++) m = fmaxf(m, wred[w * 4 + t]);
        mh[t] = m;
    }
    __syncthreads();

    if (t < RPC) {
        float4 s = p4[t];
        float p0 = __expf(s.x - mh[0]);
        float p1 = __expf(s.y - mh[1]);
        float p2 = __expf(s.z - mh[2]);
        float p3 = __expf(s.w - mh[3]);
        p4[t] = make_float4(p0, p1, p2, p3);
        float l0 = p0, l1 = p1, l2 = p2, l3 = p3;
        #pragma unroll
        for (int o = 16; o; o >>= 1) {
            l0 += __shfl_xor_sync(0xffffffffu, l0, o);
            l1 += __shfl_xor_sync(0xffffffffu, l1, o);
            l2 += __shfl_xor_sync(0xffffffffu, l2, o);
            l3 += __shfl_xor_sync(0xffffffffu, l3, o);
        }
        if (lane == 0) {
            wred[wid * 4 + 0] = l0; wred[wid * 4 + 1] = l1;
            wred[wid * 4 + 2] = l2; wred[wid * 4 + 3] = l3;
        }
    }
    __syncthreads();
    if (t < 4) {
        float l = wred[t];
        #pragma unroll
        for (int w = 1; w < 4; w++) l += wred[w * 4 + t];
        g_pm[(b * SPLIT + split) * HH + t] = mh[t];
        g_pl[(b * SPLIT + split) * HH + t] = l;
    }

    // ---- weighted key sum ----
    {
        int d = t & 63, q = t >> 6;
        float ax = 0.f, ay = 0.f, az = 0.f, aw = 0.f;
        const int kb = q * 32;
        #pragma unroll 4
        for (int kk = 0; kk < 32; kk++) {
            float kv = ks[(kb + kk) * STRIDE + d];
            float4 p = p4[kb + kk];
            ax += p.x * kv; ay += p.y * kv; az += p.z * kv; aw += p.w * kv;
        }
        accm[t] = make_float4(ax, ay, az, aw);
    }
    __syncthreads();
    if (t < 64) {
        float4 a = accm[t], c = accm[64 + t], d4 = accm[128 + t], e = accm[192 + t];
        float* gp = g_pacc + (b * SPLIT + split) * (HH * DD);
        gp[0 * DD + t] = a.x + c.x + d4.x + e.x;
        gp[1 * DD + t] = a.y + c.y + d4.y + e.y;
        gp[2 * DD + t] = a.z + c.z + d4.z + e.z;
        gp[3 * DD + t] = a.w + c.w + d4.w + e.w;
    }
}

// ============ B: combine + FFN, one CTA per batch, staged cp.async ==========
__global__ __launch_bounds__(256) void combine_ffn_kernel(
    const float* __restrict__ queries, const int* __restrict__ query_mask,
    const float* __restrict__ W_V,
    const float* __restrict__ fw1, const float* __restrict__ fw2,
    const float* __restrict__ fb1, const float* __restrict__ fb2,
    float* __restrict__ out)
{
    extern __shared__ float sm[];
    const unsigned sbase = (unsigned)__cvta_generic_to_shared(sm);
    const int b = blockIdx.x;
    const int t = threadIdx.x;

    float* wv_s   = sm + BF_WV;
    float* fw1_s  = sm + BF_FW1;
    float* fw2_s  = sm + BF_FW2;
    float* pacc_s = sm + BF_PACC;
    float* fb1_s  = sm + BF_FB1;
    float* fb2_s  = sm + BF_FB2;
    float* q_s    = sm + BF_Q0;
    float* m_s    = sm + BF_MS;
    float* l_s    = sm + BF_LS;
    float* f_s    = sm + BF_FS;
    float* sc_s   = sm + BF_SC;
    float* s_sm   = sm + BF_SSM;
    float* part_s = sm + BF_PART;
    float* res_s  = sm + BF_RES;
    float* hid_s  = sm + BF_HID;

    // G1: pacc + W_V + scalars
    {
        const float4* gp = (const float4*)(g_pacc + b * (SPLIT * HH * DD));
        const float4* gv = (const float4*)W_V;
        #pragma unroll
        for (int i = 0; i < 2; i++) {
            int idx = t + i * 256;
            CP_ASYNC16(sbase + (BF_PACC + idx * 4) * 4, gp + idx);
        }
        #pragma unroll
        for (int i = 0; i < 4; i++) {
            int idx = t + i * 256;
            CP_ASYNC16(sbase + (BF_WV + idx * 4) * 4, gv + idx);
        }
        if (t < 8) {
            CP_ASYNC16(sbase + (BF_MS + t * 4) * 4, ((const float4*)(g_pm + b * 32)) + t);
        } else if (t < 16) {
            CP_ASYNC16(sbase + (BF_LS + (t - 8) * 4) * 4, ((const float4*)(g_pl + b * 32)) + (t - 8));
        } else if (t < 32) {
            CP_ASYNC16(sbase + (BF_Q0 + (t - 16) * 4) * 4,
                       ((const float4*)(queries + (size_t)b * TT * DD)) + (t - 16));
        } else if (t < 48) {
            CP_ASYNC16(sbase + (BF_FB2 + (t - 32) * 4) * 4, ((const float4*)fb2) + (t - 32));
        } else if (t == 48) {
            CP_ASYNC16(sbase + BF_QM * 4, (const float4*)(query_mask + b * TT));
        }
        CP_COMMIT();
    }
    // G2: fw1 + fb1
    {
        const float4* g1 = (const float4*)fw1;
        #pragma unroll
        for (int i = 0; i < 16; i++) {
            int idx = t + i * 256;
            CP_ASYNC16(sbase + (BF_FW1 + idx * 4) * 4, g1 + idx);
        }
        if (t < 64) CP_ASYNC16(sbase + (BF_FB1 + t * 4) * 4, ((const float4*)fb1) + t);
        CP_COMMIT();
    }
    // G3: fw2
    {
        const float4* g2 = (const float4*)fw2;
        #pragma unroll
        for (int i = 0; i < 16; i++) {
            int idx = t + i * 256;
            CP_ASYNC16(sbase + (BF_FW2 + idx * 4) * 4, g2 + idx);
        }
        CP_COMMIT();
    }

    CP_WAIT_GROUP(2);
    __syncthreads();

    // softmax split combine (warp 0; lane = s*4+h)
    if (t < 32) {
        float m = m_s[t], lv = l_s[t];
        float M = m;
        M = fmaxf(M, __shfl_xor_sync(0xffffffffu, M, 4));
        M = fmaxf(M, __shfl_xor_sync(0xffffffffu, M, 8));
        M = fmaxf(M, __shfl_xor_sync(0xffffffffu, M, 16));
        float f = __expf(m - M);
        f_s[t] = f;
        float L = lv * f;
        L += __shfl_xor_sync(0xffffffffu, L, 4);
        L += __shfl_xor_sync(0xffffffffu, L, 8);
        L += __shfl_xor_sync(0xffffffffu, L, 16);
        if (t < 4) {
            float qm = (float)((const int*)(sm + BF_QM))[0];
            sc_s[t] = qm / L;
        }
    }
    __syncthreads();

    {
        int d = t & 63, h = t >> 6;
        float S = 0.f;
        #pragma unroll
        for (int s = 0; s < SPLIT; s++)
            S += pacc_s[s * (HH * DD) + h * DD + d] * f_s[s * HH + h];
        s_sm[h * DD + d] = S * sc_s[h];
    }
    __syncthreads();

    {
        int j = t & 63, q = t >> 6;
        int h = j >> 4;
        float a = 0.f;
        #pragma unroll
        for (int d = q * 16; d < q * 16 + 16; d++) a += s_sm[h * DD + d] * wv_s[d * 64 + j];
        part_s[t] = a;
    }
    __syncthreads();
    if (t < 64) {
        float o = part_s[t] + part_s[64 + t] + part_s[128 + t] + part_s[192 + t];
        res_s[t] = o + q_s[t];
    }
    CP_WAIT_GROUP(1);
    __syncthreads();

    {
        float a = fb1_s[t];
        #pragma unroll
        for (int j = 0; j < 64; j++) a += res_s[j] * fw1_s[j * 256 + t];
        hid_s[t] = (a > 0.f) ? a : 0.2f * a;
    }
    CP_WAIT_GROUP(0);
    __syncthreads();

    {
        int j = t & 63, mq = t >> 6;
        float a = 0.f;
        #pragma unroll
        for (int m = mq * 64; m < mq * 64 + 64; m++) a += hid_s[m] * fw2_s[m * 64 + j];
        part_s[t] = a;
    }
    __syncthreads();
    if (t < 64) {
        out[b * 64 + t] = res_s[t] + fb2_s[t]
                        + part_s[t] + part_s[64 + t] + part_s[128 + t] + part_s[192 + t];
    }
}

extern "C" void kernel_launch(void* const* d_in, const int* in_sizes, int n_in,
                              void* d_out, int out_size)
{
    const float* queries = (const float*)d_in[0];
    const float* keys    = (const float*)d_in[1];
    const int*   qmask   = (const int*)d_in[2];
    const int*   kmask   = (const int*)d_in[3];
    const float* W_Q     = (const float*)d_in[4];
    const float* W_K     = (const float*)d_in[5];
    const float* W_V     = (const float*)d_in[6];
    const float* fw1     = (const float*)d_in[7];
    const float* fw2     = (const float*)d_in[8];
    const float* fb1     = (const float*)d_in[9];
    const float* fb2     = (const float*)d_in[10];
    float* out = (float*)d_out;

    cudaFuncSetAttribute(attn_partial_kernel,
                         cudaFuncAttributeMaxDynamicSharedMemorySize, ASM_BYTES);
    cudaFuncSetAttribute(combine_ffn_kernel,
                         cudaFuncAttributeMaxDynamicSharedMemorySize, BSM_BYTES);

    attn_partial_kernel<<<dim3(SPLIT, BB), 256, ASM_BYTES>>>(queries, keys, kmask, W_Q, W_K);
    combine_ffn_kernel<<<BB, 256, BSM_BYTES>>>(queries, qmask, W_V, fw1, fw2, fb1, fb2, out);
}

// round 10
// speedup vs baseline: 1.0281x; 1.0281x over previous
#include <cuda_runtime.h>
#include <cuda_bf16.h>

#define BB 64
#define TT 1024
#define DD 64
#define HH 4
#define SPLIT 8
#define RPC 128
#define STRIDE 68
#define NEGF (-4294967296.0f)

// ---------------- kernel A smem layout (floats) ----------------
#define OFF_KS   0                // 128*68 = 8704
#define OFF_P4   8704             // 512
#define OFF_ACC  9216             // 1024 (producer u-scratch lives here early)
#define OFF_U    10240            // 256
#define OFF_WRED 10496            // 32
#define OFF_MH   10528            // 4
#define ASM_FLOATS 10532
#define ASM_BYTES (ASM_FLOATS * 4)

// ---------------- kernel B smem layout (floats) ----------------
#define BF_WV    0                // 4096
#define BF_FW1   4096             // 16384
#define BF_FW2   20480            // 16384
#define BF_PACC  36864            // 2048  ([s][h][d] planar)
#define BF_FB1   38912            // 256
#define BF_FB2   39168            // 64
#define BF_Q0    39232            // 64
#define BF_MS    39296            // 32
#define BF_LS    39328            // 32
#define BF_FS    39360            // 32
#define BF_SC    39392            // 4
#define BF_QM    39396            // 4
#define BF_SSM   39400            // 256
#define BF_PART  39656            // 256
#define BF_RES   39912            // 64
#define BF_HID   39976            // 256
#define BSM_FLOATS 40232
#define BSM_BYTES (BSM_FLOATS * 4)

#define CP_ASYNC16(dst_u32, src) \
    asm volatile("cp.async.cg.shared.global [%0], [%1], 16;" :: "r"(dst_u32), "l"(src) : "memory")
#define CP_COMMIT() asm volatile("cp.async.commit_group;" ::: "memory")
#define CP_WAIT_GROUP(n) asm volatile("cp.async.wait_group %0;" :: "n"(n) : "memory")

// cross-kernel / cross-CTA scratch
__device__ float    g_u[BB * 256];                   // [b][d*4+h]
__device__ float    g_pacc[BB * SPLIT * HH * DD];    // [b][s][h][d] planar
__device__ float    g_pm[BB * SPLIT * HH];
__device__ float    g_pl[BB * SPLIT * HH];
__device__ unsigned g_epoch[BB];                     // monotonic: u publications
__device__ unsigned g_arrive[BB];                    // monotonic: consumer arrivals

// ============ A: 8 CTAs per batch; split==0 produces u, others spin ========
__global__ __launch_bounds__(256, 4)
void attn_partial_kernel(
    const float* __restrict__ queries, const float* __restrict__ keys,
    const int* __restrict__ key_mask,
    const float* __restrict__ W_Q, const float* __restrict__ W_K)
{
    extern __shared__ float sm[];
    const unsigned sbase = (unsigned)__cvta_generic_to_shared(sm);

    float*  ks   = sm + OFF_KS;
    float4* p4   = (float4*)(sm + OFF_P4);
    float4* accm = (float4*)(sm + OFF_ACC);
    float*  u    = sm + OFF_U;
    float*  wred = sm + OFF_WRED;
    float*  mh   = sm + OFF_MH;
    __shared__ unsigned s_replay;

    const int split = blockIdx.x;
    const int b     = blockIdx.y;
    const int t     = threadIdx.x;
    const int k0    = split * RPC;
    const int lane  = t & 31;
    const int wid   = t >> 5;

    // ---- key tile DMA: 128 rows x 16 f4, 8 per thread (all CTAs) ----
    {
        const float4* kg = (const float4*)(keys + ((size_t)b * TT + k0) * DD);
        #pragma unroll
        for (int i = 0; i < 8; i++) {
            int idx = t + i * 256;
            int row = idx >> 4, c = idx & 15;
            CP_ASYNC16(sbase + (row * STRIDE + c * 4) * 4, kg + idx);
        }
        CP_COMMIT();
    }
    int kmv = 1;
    if (t < RPC) kmv = key_mask[b * TT + k0 + t];

    if (split == 0) {
        // ---- producer: compute u = 0.25 * W_K-fold of (q0 @ W_Q) ----
        float* part = sm + OFF_ACC;          // 256 (dead until weighted sum)
        float* q0   = sm + OFF_ACC + 256;    // 64
        float* Qh   = sm + OFF_ACC + 320;    // 64

        if (t < 16) ((float4*)q0)[t] = ((const float4*)(queries + (size_t)b * TT * DD))[t];
        __syncthreads();
        {
            int j = t & 63, q = t >> 6;
            float a = 0.f;
            #pragma unroll
            for (int i = q * 16; i < q * 16 + 16; i++) a += q0[i] * W_Q[i * 64 + j];
            part[t] = a;
        }
        __syncthreads();
        if (t < 64) Qh[t] = part[t] + part[64 + t] + part[128 + t] + part[192 + t];
        __syncthreads();
        {
            int d = t & 63, h = t >> 6;
            const float4* wr  = (const float4*)(W_K + d * 64 + h * 16);
            const float4* qh4 = (const float4*)(Qh + h * 16);
            float s = 0.f;
            #pragma unroll
            for (int c = 0; c < 4; c++) {
                float4 w = wr[c]; float4 q = qh4[c];
                s += w.x * q.x + w.y * q.y + w.z * q.z + w.w * q.w;
            }
            s *= 0.25f;
            u[d * 4 + h] = s;                 // local copy
            g_u[b * 256 + d * 4 + h] = s;     // publish
        }
        __threadfence();
        __syncthreads();
        if (t == 0) atomicAdd(&g_epoch[b], 1u);
    } else {
        // ---- consumer: derive replay index, wait for this replay's u ----
        if (t == 0) {
            unsigned old = atomicAdd(&g_arrive[b], 1u);
            unsigned r = old / (SPLIT - 1);   // 7 consumers per batch per replay
            while (*(volatile unsigned*)&g_epoch[b] <= r) __nanosleep(32);
            __threadfence();
            s_replay = 1u;   // dummy publish to order via syncthreads
        }
        __syncthreads();
        if (t < 64) ((float4*)u)[t] = ((const float4*)g_u)[b * 64 + t];
    }
    CP_WAIT_GROUP(0);
    __syncthreads();

    // ---- scores for key row t (threads 0..127), 4 heads ----
    if (t < RPC) {
        const float4* krow = (const float4*)&ks[t * STRIDE];
        const float4* u4 = (const float4*)u;
        float a0 = 0.f, a1 = 0.f, a2 = 0.f, a3 = 0.f;
        #pragma unroll
        for (int c = 0; c < 16; c++) {
            float4 kv = krow[c];
            float4 ux = u4[4 * c + 0], uy = u4[4 * c + 1];
            float4 uz = u4[4 * c + 2], uw = u4[4 * c + 3];
            a0 += kv.x * ux.x + kv.y * uy.x + kv.z * uz.x + kv.w * uw.x;
            a1 += kv.x * ux.y + kv.y * uy.y + kv.z * uz.y + kv.w * uw.y;
            a2 += kv.x * ux.z + kv.y * uy.z + kv.z * uz.z + kv.w * uw.z;
            a3 += kv.x * ux.w + kv.y * uy.w + kv.z * uz.w + kv.w * uw.w;
        }
        bool masked = (kmv != 1) || ((k0 + t) == 0);
        float s0 = masked ? NEGF : a0;
        float s1 = masked ? NEGF : a1;
        float s2 = masked ? NEGF : a2;
        float s3 = masked ? NEGF : a3;

        float m0 = s0, m1 = s1, m2 = s2, m3 = s3;
        #pragma unroll
        for (int o = 16; o; o >>= 1) {
            m0 = fmaxf(m0, __shfl_xor_sync(0xffffffffu, m0, o));
            m1 = fmaxf(m1, __shfl_xor_sync(0xffffffffu, m1, o));
            m2 = fmaxf(m2, __shfl_xor_sync(0xffffffffu, m2, o));
            m3 = fmaxf(m3, __shfl_xor_sync(0xffffffffu, m3, o));
        }
        if (lane == 0) {
            wred[wid * 4 + 0] = m0; wred[wid * 4 + 1] = m1;
            wred[wid * 4 + 2] = m2; wred[wid * 4 + 3] = m3;
        }
        p4[t] = make_float4(s0, s1, s2, s3);
    }
    __syncthreads();
    if (t < 4) {
        float m = wred[t];
        #pragma unroll
        for (int w = 1; w < 4; w++) m = fmaxf(m, wred[w * 4 + t]);
        mh[t] = m;
    }
    __syncthreads();

    if (t < RPC) {
        float4 s = p4[t];
        float p0 = __expf(s.x - mh[0]);
        float p1 = __expf(s.y - mh[1]);
        float p2 = __expf(s.z - mh[2]);
        float p3 = __expf(s.w - mh[3]);
        p4[t] = make_float4(p0, p1, p2, p3);
        float l0 = p0, l1 = p1, l2 = p2, l3 = p3;
        #pragma unroll
        for (int o = 16; o; o >>= 1) {
            l0 += __shfl_xor_sync(0xffffffffu, l0, o);
            l1 += __shfl_xor_sync(0xffffffffu, l1, o);
            l2 += __shfl_xor_sync(0xffffffffu, l2, o);
            l3 += __shfl_xor_sync(0xffffffffu, l3, o);
        }
        if (lane == 0) {
            wred[wid * 4 + 0] = l0; wred[wid * 4 + 1] = l1;
            wred[wid * 4 + 2] = l2; wred[wid * 4 + 3] = l3;
        }
    }
    __syncthreads();
    if (t < 4) {
        float l = wred[t];
        #pragma unroll
        for (int w = 1; w < 4; w++) l += wred[w * 4 + t];
        g_pm[(b * SPLIT + split) * HH + t] = mh[t];
        g_pl[(b * SPLIT + split) * HH + t] = l;
    }

    // ---- weighted key sum ----
    {
        int d = t & 63, q = t >> 6;
        float ax = 0.f, ay = 0.f, az = 0.f, aw = 0.f;
        const int kb = q * 32;
        #pragma unroll 4
        for (int kk = 0; kk < 32; kk++) {
            float kv = ks[(kb + kk) * STRIDE + d];
            float4 p = p4[kb + kk];
            ax += p.x * kv; ay += p.y * kv; az += p.z * kv; aw += p.w * kv;
        }
        accm[t] = make_float4(ax, ay, az, aw);
    }
    __syncthreads();
    if (t < 64) {
        float4 a = accm[t], c = accm[64 + t], d4 = accm[128 + t], e = accm[192 + t];
        float* gp = g_pacc + (b * SPLIT + split) * (HH * DD);
        gp[0 * DD + t] = a.x + c.x + d4.x + e.x;
        gp[1 * DD + t] = a.y + c.y + d4.y + e.y;
        gp[2 * DD + t] = a.z + c.z + d4.z + e.z;
        gp[3 * DD + t] = a.w + c.w + d4.w + e.w;
    }
}

// ============ B: combine + FFN, one CTA per batch, staged cp.async ==========
__global__ __launch_bounds__(256) void combine_ffn_kernel(
    const float* __restrict__ queries, const int* __restrict__ query_mask,
    const float* __restrict__ W_V,
    const float* __restrict__ fw1, const float* __restrict__ fw2,
    const float* __restrict__ fb1, const float* __restrict__ fb2,
    float* __restrict__ out)
{
    extern __shared__ float sm[];
    const unsigned sbase = (unsigned)__cvta_generic_to_shared(sm);
    const int b = blockIdx.x;
    const int t = threadIdx.x;

    float* wv_s   = sm + BF_WV;
    float* fw1_s  = sm + BF_FW1;
    float* fw2_s  = sm + BF_FW2;
    float* pacc_s = sm + BF_PACC;
    float* fb1_s  = sm + BF_FB1;
    float* fb2_s  = sm + BF_FB2;
    float* q_s    = sm + BF_Q0;
    float* m_s    = sm + BF_MS;
    float* l_s    = sm + BF_LS;
    float* f_s    = sm + BF_FS;
    float* sc_s   = sm + BF_SC;
    float* s_sm   = sm + BF_SSM;
    float* part_s = sm + BF_PART;
    float* res_s  = sm + BF_RES;
    float* hid_s  = sm + BF_HID;

    // G1: pacc + W_V + scalars
    {
        const float4* gp = (const float4*)(g_pacc + b * (SPLIT * HH * DD));
        const float4* gv = (const float4*)W_V;
        #pragma unroll
        for (int i = 0; i < 2; i++) {
            int idx = t + i * 256;
            CP_ASYNC16(sbase + (BF_PACC + idx * 4) * 4, gp + idx);
        }
        #pragma unroll
        for (int i = 0; i < 4; i++) {
            int idx = t + i * 256;
            CP_ASYNC16(sbase + (BF_WV + idx * 4) * 4, gv + idx);
        }
        if (t < 8) {
            CP_ASYNC16(sbase + (BF_MS + t * 4) * 4, ((const float4*)(g_pm + b * 32)) + t);
        } else if (t < 16) {
            CP_ASYNC16(sbase + (BF_LS + (t - 8) * 4) * 4, ((const float4*)(g_pl + b * 32)) + (t - 8));
        } else if (t < 32) {
            CP_ASYNC16(sbase + (BF_Q0 + (t - 16) * 4) * 4,
                       ((const float4*)(queries + (size_t)b * TT * DD)) + (t - 16));
        } else if (t < 48) {
            CP_ASYNC16(sbase + (BF_FB2 + (t - 32) * 4) * 4, ((const float4*)fb2) + (t - 32));
        } else if (t == 48) {
            CP_ASYNC16(sbase + BF_QM * 4, (const float4*)(query_mask + b * TT));
        }
        CP_COMMIT();
    }
    // G2: fw1 + fb1
    {
        const float4* g1 = (const float4*)fw1;
        #pragma unroll
        for (int i = 0; i < 16; i++) {
            int idx = t + i * 256;
            CP_ASYNC16(sbase + (BF_FW1 + idx * 4) * 4, g1 + idx);
        }
        if (t < 64) CP_ASYNC16(sbase + (BF_FB1 + t * 4) * 4, ((const float4*)fb1) + t);
        CP_COMMIT();
    }
    // G3: fw2
    {
        const float4* g2 = (const float4*)fw2;
        #pragma unroll
        for (int i = 0; i < 16; i++) {
            int idx = t + i * 256;
            CP_ASYNC16(sbase + (BF_FW2 + idx * 4) * 4, g2 + idx);
        }
        CP_COMMIT();
    }

    CP_WAIT_GROUP(2);
    __syncthreads();

    // softmax split combine (warp 0; lane = s*4+h)
    if (t < 32) {
        float m = m_s[t], lv = l_s[t];
        float M = m;
        M = fmaxf(M, __shfl_xor_sync(0xffffffffu, M, 4));
        M = fmaxf(M, __shfl_xor_sync(0xffffffffu, M, 8));
        M = fmaxf(M, __shfl_xor_sync(0xffffffffu, M, 16));
        float f = __expf(m - M);
        f_s[t] = f;
        float L = lv * f;
        L += __shfl_xor_sync(0xffffffffu, L, 4);
        L += __shfl_xor_sync(0xffffffffu, L, 8);
        L += __shfl_xor_sync(0xffffffffu, L, 16);
        if (t < 4) {
            float qm = (float)((const int*)(sm + BF_QM))[0];
            sc_s[t] = qm / L;
        }
    }
    __syncthreads();

    {
        int d = t & 63, h = t >> 6;
        float S = 0.f;
        #pragma unroll
        for (int s = 0; s < SPLIT; s++)
            S += pacc_s[s * (HH * DD) + h * DD + d] * f_s[s * HH + h];
        s_sm[h * DD + d] = S * sc_s[h];
    }
    __syncthreads();

    {
        int j = t & 63, q = t >> 6;
        int h = j >> 4;
        float a = 0.f;
        #pragma unroll
        for (int d = q * 16; d < q * 16 + 16; d++) a += s_sm[h * DD + d] * wv_s[d * 64 + j];
        part_s[t] = a;
    }
    __syncthreads();
    if (t < 64) {
        float o = part_s[t] + part_s[64 + t] + part_s[128 + t] + part_s[192 + t];
        res_s[t] = o + q_s[t];
    }
    CP_WAIT_GROUP(1);
    __syncthreads();

    {
        float a = fb1_s[t];
        #pragma unroll
        for (int j = 0; j < 64; j++) a += res_s[j] * fw1_s[j * 256 + t];
        hid_s[t] = (a > 0.f) ? a : 0.2f * a;
    }
    CP_WAIT_GROUP(0);
    __syncthreads();

    {
        int j = t & 63, mq = t >> 6;
        float a = 0.f;
        #pragma unroll
        for (int m = mq * 64; m < mq * 64 + 64; m++) a += hid_s[m] * fw2_s[m * 64 + j];
        part_s[t] = a;
    }
    __syncthreads();
    if (t < 64) {
        out[b * 64 + t] = res_s[t] + fb2_s[t]
                        + part_s[t] + part_s[64 + t] + part_s[128 + t] + part_s[192 + t];
    }
}

extern "C" void kernel_launch(void* const* d_in, const int* in_sizes, int n_in,
                              void* d_out, int out_size)
{
    const float* queries = (const float*)d_in[0];
    const float* keys    = (const float*)d_in[1];
    const int*   qmask   = (const int*)d_in[2];
    const int*   kmask   = (const int*)d_in[3];
    const float* W_Q     = (const float*)d_in[4];
    const float* W_K     = (const float*)d_in[5];
    const float* W_V     = (const float*)d_in[6];
    const float* fw1     = (const float*)d_in[7];
    const float* fw2     = (const float*)d_in[8];
    const float* fb1     = (const float*)d_in[9];
    const float* fb2     = (const float*)d_in[10];
    float* out = (float*)d_out;

    cudaFuncSetAttribute(attn_partial_kernel,
                         cudaFuncAttributeMaxDynamicSharedMemorySize, ASM_BYTES);
    cudaFuncSetAttribute(combine_ffn_kernel,
                         cudaFuncAttributeMaxDynamicSharedMemorySize, BSM_BYTES);

    attn_partial_kernel<<<dim3(SPLIT, BB), 256, ASM_BYTES>>>(queries, keys, kmask, W_Q, W_K);
    combine_ffn_kernel<<<BB, 256, BSM_BYTES>>>(queries, qmask, W_V, fw1, fw2, fb1, fb2, out);
}